// round 2
// baseline (speedup 1.0000x reference)
#include <cuda_runtime.h>
#include <cstdint>

// ODE-RNN fused persistent scan kernel (fp32 baseline).
// B=2048 rows, 199 steps. 128 CTAs x 256 threads, 16 rows per CTA.

#define R_PER_CTA 16
#define NSTEPS 199
#define TT 200
#define DD 64
#define HH 100

__device__ __forceinline__ float sigmoidf_fast(float x) {
    return 1.0f / (1.0f + __expf(-x));
}

// Accumulate a 2-row x 2-col output tile over K (K % 4 == 0).
// w points at W[0][n0]; LDW is the row stride of W (= its N).
// s0/s1 point at the two source rows (contiguous k, 16B aligned).
template<int K, int LDW>
__device__ __forceinline__ void accum_tile(
    const float* __restrict__ w,
    const float* __restrict__ s0,
    const float* __restrict__ s1,
    float& a00, float& a01, float& a10, float& a11)
{
#pragma unroll
    for (int k = 0; k < K; k += 4) {
        float4 y0 = *reinterpret_cast<const float4*>(s0 + k);
        float4 y1 = *reinterpret_cast<const float4*>(s1 + k);
        float2 w0 = *reinterpret_cast<const float2*>(w + (k + 0) * LDW);
        float2 w1 = *reinterpret_cast<const float2*>(w + (k + 1) * LDW);
        float2 w2 = *reinterpret_cast<const float2*>(w + (k + 2) * LDW);
        float2 w3 = *reinterpret_cast<const float2*>(w + (k + 3) * LDW);
        a00 = fmaf(y0.x, w0.x, a00); a01 = fmaf(y0.x, w0.y, a01);
        a10 = fmaf(y1.x, w0.x, a10); a11 = fmaf(y1.x, w0.y, a11);
        a00 = fmaf(y0.y, w1.x, a00); a01 = fmaf(y0.y, w1.y, a01);
        a10 = fmaf(y1.y, w1.x, a10); a11 = fmaf(y1.y, w1.y, a11);
        a00 = fmaf(y0.z, w2.x, a00); a01 = fmaf(y0.z, w2.y, a01);
        a10 = fmaf(y1.z, w2.x, a10); a11 = fmaf(y1.z, w2.y, a11);
        a00 = fmaf(y0.w, w3.x, a00); a01 = fmaf(y0.w, w3.y, a01);
        a10 = fmaf(y1.w, w3.x, a10); a11 = fmaf(y1.w, w3.y, a11);
    }
}

__global__ void __launch_bounds__(256, 1) ode_rnn_kernel(
    const float* __restrict__ data, const float* __restrict__ ts,
    const float* __restrict__ Wf1, const float* __restrict__ bf1,
    const float* __restrict__ Wf2, const float* __restrict__ bf2,
    const float* __restrict__ Wz1, const float* __restrict__ bz1,
    const float* __restrict__ Wz2, const float* __restrict__ bz2,
    const float* __restrict__ Wr1, const float* __restrict__ br1,
    const float* __restrict__ Wr2, const float* __restrict__ br2,
    const float* __restrict__ Wh1, const float* __restrict__ bh1,
    const float* __restrict__ Wh2, const float* __restrict__ bh2,
    float* __restrict__ yi_out, float* __restrict__ lat_out)
{
    // Padded strides for conflict-free multi-row float4 LDS.
    __shared__ float sY [R_PER_CTA][68];   // current latent y
    __shared__ float sYO[R_PER_CTA][68];   // y_ode
    __shared__ float sC [R_PER_CTA][132];  // concat buffer: [0:64)=y_ode (later y_ode*r), [64:128)=x
    __shared__ float sH [R_PER_CTA][204];  // hidden activations (up to 200)
    __shared__ float sZR[R_PER_CTA][132];  // [0:64)=z, [64:128)=r
    __shared__ float sbf1[HH], sbz1[HH], sbr1[HH], sbh1[HH];
    __shared__ float sbf2[DD], sbz2[DD], sbr2[DD], sbh2[DD];
    __shared__ float sts[TT];

    const int tid = threadIdx.x;
    const int rowbase = blockIdx.x * R_PER_CTA;

    // ---- one-time init ----
    for (int i = tid; i < HH; i += 256) {
        sbf1[i] = bf1[i]; sbz1[i] = bz1[i]; sbr1[i] = br1[i]; sbh1[i] = bh1[i];
    }
    for (int i = tid; i < DD; i += 256) {
        sbf2[i] = bf2[i]; sbz2[i] = bz2[i]; sbr2[i] = br2[i]; sbh2[i] = bh2[i];
    }
    for (int i = tid; i < TT; i += 256) sts[i] = ts[i];
    for (int i = tid; i < R_PER_CTA * 68; i += 256) (&sY[0][0])[i] = 0.0f;
    __syncthreads();

    const int cr  = tid >> 4;          // 0..15 (row for copy ops)
    const int cd4 = (tid & 15) * 4;    // 0..60 step 4

    for (int step = 0; step < NSTEPS; ++step) {
        const float dt = (step == 0) ? (sts[1] - sts[0]) : (sts[step - 1] - sts[step]);

        // load x(t=step+1) into sC[:,64:128) (coalesced float4)
        {
            const float4 v = *reinterpret_cast<const float4*>(
                data + (((size_t)(rowbase + cr)) * TT + (step + 1)) * DD + cd4);
            *reinterpret_cast<float4*>(&sC[cr][64 + cd4]) = v;
        }

        // ---- P1: sH[r][0:100) = tanh(bf1 + Y @ Wf1), K=64 ----
        for (int t = tid; t < 8 * 50; t += 256) {
            const int r0 = (t / 50) * 2, n0 = (t % 50) * 2;
            float a00 = 0.f, a01 = 0.f, a10 = 0.f, a11 = 0.f;
            accum_tile<64, 100>(Wf1 + n0, &sY[r0][0], &sY[r0 + 1][0], a00, a01, a10, a11);
            sH[r0    ][n0    ] = tanhf(a00 + sbf1[n0    ]);
            sH[r0    ][n0 + 1] = tanhf(a01 + sbf1[n0 + 1]);
            sH[r0 + 1][n0    ] = tanhf(a10 + sbf1[n0    ]);
            sH[r0 + 1][n0 + 1] = tanhf(a11 + sbf1[n0 + 1]);
        }
        __syncthreads();

        // ---- P2: y_ode = Y + dt*(bf2 + H @ Wf2), K=100, N=64 ----
        {
            const int r0 = (tid / 32) * 2, n0 = (tid % 32) * 2;
            float a00 = 0.f, a01 = 0.f, a10 = 0.f, a11 = 0.f;
            accum_tile<100, 64>(Wf2 + n0, &sH[r0][0], &sH[r0 + 1][0], a00, a01, a10, a11);
            float v;
            v = sY[r0    ][n0    ] + dt * (a00 + sbf2[n0    ]); sYO[r0    ][n0    ] = v; sC[r0    ][n0    ] = v;
            v = sY[r0    ][n0 + 1] + dt * (a01 + sbf2[n0 + 1]); sYO[r0    ][n0 + 1] = v; sC[r0    ][n0 + 1] = v;
            v = sY[r0 + 1][n0    ] + dt * (a10 + sbf2[n0    ]); sYO[r0 + 1][n0    ] = v; sC[r0 + 1][n0    ] = v;
            v = sY[r0 + 1][n0 + 1] + dt * (a11 + sbf2[n0 + 1]); sYO[r0 + 1][n0 + 1] = v; sC[r0 + 1][n0 + 1] = v;
        }
        __syncthreads();

        // ---- P3: sH[r][n] = tanh(b + C @ W1), n<100 -> z-net (Wz1), n>=100 -> r-net (Wr1); K=128 ----
        for (int t = tid; t < 8 * 100; t += 256) {
            const int r0 = (t / 100) * 2, n0 = (t % 100) * 2;
            float a00 = 0.f, a01 = 0.f, a10 = 0.f, a11 = 0.f;
            if (n0 < 100) {
                accum_tile<128, 100>(Wz1 + n0, &sC[r0][0], &sC[r0 + 1][0], a00, a01, a10, a11);
                sH[r0    ][n0    ] = tanhf(a00 + sbz1[n0    ]);
                sH[r0    ][n0 + 1] = tanhf(a01 + sbz1[n0 + 1]);
                sH[r0 + 1][n0    ] = tanhf(a10 + sbz1[n0    ]);
                sH[r0 + 1][n0 + 1] = tanhf(a11 + sbz1[n0 + 1]);
            } else {
                const int m0 = n0 - 100;
                accum_tile<128, 100>(Wr1 + m0, &sC[r0][0], &sC[r0 + 1][0], a00, a01, a10, a11);
                sH[r0    ][n0    ] = tanhf(a00 + sbr1[m0    ]);
                sH[r0    ][n0 + 1] = tanhf(a01 + sbr1[m0 + 1]);
                sH[r0 + 1][n0    ] = tanhf(a10 + sbr1[m0    ]);
                sH[r0 + 1][n0 + 1] = tanhf(a11 + sbr1[m0 + 1]);
            }
        }
        __syncthreads();

        // ---- P4: z = sigmoid(bz2 + Hz @ Wz2), r = sigmoid(br2 + Hr @ Wr2); K=100, N=64 each ----
        for (int t = tid; t < 512; t += 256) {
            const int g = t >> 8;              // 0 = z, 1 = r
            const int local = t & 255;
            const int r0 = (local / 32) * 2, n0 = (local % 32) * 2;
            const float* w = g ? (Wr2 + n0) : (Wz2 + n0);
            const float* s0 = &sH[r0][g * 100];
            const float* s1 = &sH[r0 + 1][g * 100];
            float a00 = 0.f, a01 = 0.f, a10 = 0.f, a11 = 0.f;
            accum_tile<100, 64>(w, s0, s1, a00, a01, a10, a11);
            const float b0 = g ? sbr2[n0] : sbz2[n0];
            const float b1 = g ? sbr2[n0 + 1] : sbz2[n0 + 1];
            const int o = g * 64 + n0;
            sZR[r0    ][o    ] = sigmoidf_fast(a00 + b0);
            sZR[r0    ][o + 1] = sigmoidf_fast(a01 + b1);
            sZR[r0 + 1][o    ] = sigmoidf_fast(a10 + b0);
            sZR[r0 + 1][o + 1] = sigmoidf_fast(a11 + b1);
        }
        __syncthreads();

        // ---- P5: sC[:,0:64) = y_ode * r (elementwise) ----
        {
#pragma unroll
            for (int j = 0; j < 4; ++j)
                sC[cr][cd4 + j] = sYO[cr][cd4 + j] * sZR[cr][64 + cd4 + j];
        }
        __syncthreads();

        // ---- P6: sH[r][0:100) = tanh(bh1 + CH @ Wh1), K=128 ----
        for (int t = tid; t < 8 * 50; t += 256) {
            const int r0 = (t / 50) * 2, n0 = (t % 50) * 2;
            float a00 = 0.f, a01 = 0.f, a10 = 0.f, a11 = 0.f;
            accum_tile<128, 100>(Wh1 + n0, &sC[r0][0], &sC[r0 + 1][0], a00, a01, a10, a11);
            sH[r0    ][n0    ] = tanhf(a00 + sbh1[n0    ]);
            sH[r0    ][n0 + 1] = tanhf(a01 + sbh1[n0 + 1]);
            sH[r0 + 1][n0    ] = tanhf(a10 + sbh1[n0    ]);
            sH[r0 + 1][n0 + 1] = tanhf(a11 + sbh1[n0 + 1]);
        }
        __syncthreads();

        // ---- P7: h = tanh(bh2 + H @ Wh2); y = (1-z)*h + z*y_ode; K=100, N=64 ----
        {
            const int r0 = (tid / 32) * 2, n0 = (tid % 32) * 2;
            float a00 = 0.f, a01 = 0.f, a10 = 0.f, a11 = 0.f;
            accum_tile<100, 64>(Wh2 + n0, &sH[r0][0], &sH[r0 + 1][0], a00, a01, a10, a11);
#pragma unroll
            for (int q = 0; q < 4; ++q) {
                const int rr = r0 + (q >> 1);
                const int nn = n0 + (q & 1);
                const float a = (q == 0) ? a00 : (q == 1) ? a01 : (q == 2) ? a10 : a11;
                const float h = tanhf(a + sbh2[nn]);
                const float z = sZR[rr][nn];
                const float yo = sYO[rr][nn];
                sY[rr][nn] = (1.0f - z) * h + z * yo;
            }
        }
        __syncthreads();

        // ---- write latent_ys[b][step][:] (coalesced float4) ----
        if (lat_out) {
            const float4 v = *reinterpret_cast<const float4*>(&sY[cr][cd4]);
            *reinterpret_cast<float4*>(
                lat_out + (((size_t)(rowbase + cr)) * NSTEPS + step) * DD + cd4) = v;
        }
        __syncthreads();
    }

    // final state yi
    if (yi_out) {
        const float4 v = *reinterpret_cast<const float4*>(&sY[cr][cd4]);
        *reinterpret_cast<float4*>(yi_out + ((size_t)(rowbase + cr)) * DD + cd4) = v;
    }
}

extern "C" void kernel_launch(void* const* d_in, const int* in_sizes, int n_in,
                              void* d_out, int out_size)
{
    const float* data = (const float*)d_in[0];
    const float* ts   = (const float*)d_in[1];
    const float* Wf1  = (const float*)d_in[2];
    const float* bf1  = (const float*)d_in[3];
    const float* Wf2  = (const float*)d_in[4];
    const float* bf2  = (const float*)d_in[5];
    const float* Wz1  = (const float*)d_in[6];
    const float* bz1  = (const float*)d_in[7];
    const float* Wz2  = (const float*)d_in[8];
    const float* bz2  = (const float*)d_in[9];
    const float* Wr1  = (const float*)d_in[10];
    const float* br1  = (const float*)d_in[11];
    const float* Wr2  = (const float*)d_in[12];
    const float* br2  = (const float*)d_in[13];
    const float* Wh1  = (const float*)d_in[14];
    const float* bh1  = (const float*)d_in[15];
    const float* Wh2  = (const float*)d_in[16];
    const float* bh2  = (const float*)d_in[17];

    const long long latN = 2048LL * 199 * 64;   // 26,083,328
    const long long yiN  = 2048LL * 64;         // 131,072
    float* out = (float*)d_out;
    float* yi_out = nullptr;
    float* lat_out = nullptr;
    if ((long long)out_size == latN + yiN) { yi_out = out; lat_out = out + yiN; }
    else if ((long long)out_size == latN)  { lat_out = out; }
    else if ((long long)out_size == yiN)   { yi_out = out; }
    else if ((long long)out_size > latN)   { yi_out = out; lat_out = out + yiN; }
    else                                   { lat_out = out; }

    ode_rnn_kernel<<<128, 256>>>(
        data, ts, Wf1, bf1, Wf2, bf2, Wz1, bz1, Wz2, bz2,
        Wr1, br1, Wr2, br2, Wh1, bh1, Wh2, bh2, yi_out, lat_out);
}

// round 3
// speedup vs baseline: 1.3286x; 1.3286x over previous
#include <cuda_runtime.h>
#include <cstdint>

// ODE-RNN fused persistent scan kernel, round 3.
// B=2048 rows, 199 steps. 128 CTAs x 256 threads, 16 rows per CTA.
// Key changes vs R2: packed f32x2 FMAs (2 cols per accumulator), larger
// row-tiles (4r x 4c on the K=128 phases), coltile-fastest lane order so
// activation LDS are warp broadcasts, P5 folded into P4, 6 syncs/step.

#define R_PER_CTA 16
#define NSTEPS 199
#define TT 200
#define DD 64
#define HH 100

typedef unsigned long long u64;

__device__ __forceinline__ void fma2(u64& d, u64 a, u64 b) {
    asm("fma.rn.f32x2 %0, %1, %2, %0;" : "+l"(d) : "l"(a), "l"(b));
}
__device__ __forceinline__ u64 dup2(float x) {
    u64 r; asm("mov.b64 %0, {%1, %1};" : "=l"(r) : "f"(x)); return r;
}
__device__ __forceinline__ float2 unpack2(u64 v) {
    float2 r; asm("mov.b64 {%0, %1}, %2;" : "=f"(r.x), "=f"(r.y) : "l"(v)); return r;
}
__device__ __forceinline__ float sigmoidf_fast(float x) {
    return 1.0f / (1.0f + __expf(-x));
}

// 2-row x 4-col tile, cols packed pairwise into f32x2 accumulators.
// acc[0..1] = row0 {n0,n0+1},{n0+2,n0+3}; acc[2..3] = row1.
template<int K, int LDW>
__device__ __forceinline__ void tile2x4(
    const float* __restrict__ w,
    const float* __restrict__ s0, const float* __restrict__ s1,
    u64 acc[4])
{
#pragma unroll
    for (int k = 0; k < K; k += 4) {
        const float4 y0 = *reinterpret_cast<const float4*>(s0 + k);
        const float4 y1 = *reinterpret_cast<const float4*>(s1 + k);
        const float y0a[4] = {y0.x, y0.y, y0.z, y0.w};
        const float y1a[4] = {y1.x, y1.y, y1.z, y1.w};
#pragma unroll
        for (int j = 0; j < 4; ++j) {
            const ulonglong2 wv = *reinterpret_cast<const ulonglong2*>(w + (k + j) * LDW);
            const u64 d0 = dup2(y0a[j]);
            const u64 d1 = dup2(y1a[j]);
            fma2(acc[0], d0, wv.x); fma2(acc[1], d0, wv.y);
            fma2(acc[2], d1, wv.x); fma2(acc[3], d1, wv.y);
        }
    }
}

// 4-row x 4-col tile. acc[r*2+c].
template<int K, int LDW>
__device__ __forceinline__ void tile4x4(
    const float* __restrict__ w,
    const float* __restrict__ s0, const float* __restrict__ s1,
    const float* __restrict__ s2, const float* __restrict__ s3,
    u64 acc[8])
{
#pragma unroll
    for (int k = 0; k < K; k += 4) {
        const float4 y0 = *reinterpret_cast<const float4*>(s0 + k);
        const float4 y1 = *reinterpret_cast<const float4*>(s1 + k);
        const float4 y2 = *reinterpret_cast<const float4*>(s2 + k);
        const float4 y3 = *reinterpret_cast<const float4*>(s3 + k);
        const float y0a[4] = {y0.x, y0.y, y0.z, y0.w};
        const float y1a[4] = {y1.x, y1.y, y1.z, y1.w};
        const float y2a[4] = {y2.x, y2.y, y2.z, y2.w};
        const float y3a[4] = {y3.x, y3.y, y3.z, y3.w};
#pragma unroll
        for (int j = 0; j < 4; ++j) {
            const ulonglong2 wv = *reinterpret_cast<const ulonglong2*>(w + (k + j) * LDW);
            const u64 d0 = dup2(y0a[j]);
            const u64 d1 = dup2(y1a[j]);
            const u64 d2 = dup2(y2a[j]);
            const u64 d3 = dup2(y3a[j]);
            fma2(acc[0], d0, wv.x); fma2(acc[1], d0, wv.y);
            fma2(acc[2], d1, wv.x); fma2(acc[3], d1, wv.y);
            fma2(acc[4], d2, wv.x); fma2(acc[5], d2, wv.y);
            fma2(acc[6], d3, wv.x); fma2(acc[7], d3, wv.y);
        }
    }
}

// 2-row x 2-col tile. acc[0]=row0, acc[1]=row1.
template<int K, int LDW>
__device__ __forceinline__ void tile2x2(
    const float* __restrict__ w,
    const float* __restrict__ s0, const float* __restrict__ s1,
    u64 acc[2])
{
#pragma unroll
    for (int k = 0; k < K; k += 4) {
        const float4 y0 = *reinterpret_cast<const float4*>(s0 + k);
        const float4 y1 = *reinterpret_cast<const float4*>(s1 + k);
        const float y0a[4] = {y0.x, y0.y, y0.z, y0.w};
        const float y1a[4] = {y1.x, y1.y, y1.z, y1.w};
#pragma unroll
        for (int j = 0; j < 4; ++j) {
            const u64 wv = *reinterpret_cast<const u64*>(w + (k + j) * LDW);
            fma2(acc[0], dup2(y0a[j]), wv);
            fma2(acc[1], dup2(y1a[j]), wv);
        }
    }
}

__global__ void __launch_bounds__(256, 1) ode_rnn_kernel(
    const float* __restrict__ data, const float* __restrict__ ts,
    const float* __restrict__ Wf1, const float* __restrict__ bf1,
    const float* __restrict__ Wf2, const float* __restrict__ bf2,
    const float* __restrict__ Wz1, const float* __restrict__ bz1,
    const float* __restrict__ Wz2, const float* __restrict__ bz2,
    const float* __restrict__ Wr1, const float* __restrict__ br1,
    const float* __restrict__ Wr2, const float* __restrict__ br2,
    const float* __restrict__ Wh1, const float* __restrict__ bh1,
    const float* __restrict__ Wh2, const float* __restrict__ bh2,
    float* __restrict__ yi_out, float* __restrict__ lat_out)
{
    __shared__ float sY [R_PER_CTA][68];   // current latent y
    __shared__ float sYO[R_PER_CTA][68];   // y_ode
    __shared__ float sC [R_PER_CTA][132];  // [0:64)=y_ode (later y_ode*r), [64:128)=x
    __shared__ float sH [R_PER_CTA][204];  // hidden activations (up to 200)
    __shared__ float sZ [R_PER_CTA][68];   // z gate
    __shared__ float sbf1[HH], sbz1[HH], sbr1[HH], sbh1[HH];
    __shared__ float sbf2[DD], sbz2[DD], sbr2[DD], sbh2[DD];
    __shared__ float sts[TT];

    const int tid = threadIdx.x;
    const int rowbase = blockIdx.x * R_PER_CTA;

    for (int i = tid; i < HH; i += 256) {
        sbf1[i] = bf1[i]; sbz1[i] = bz1[i]; sbr1[i] = br1[i]; sbh1[i] = bh1[i];
    }
    for (int i = tid; i < DD; i += 256) {
        sbf2[i] = bf2[i]; sbz2[i] = bz2[i]; sbr2[i] = br2[i]; sbh2[i] = bh2[i];
    }
    for (int i = tid; i < TT; i += 256) sts[i] = ts[i];
    for (int i = tid; i < R_PER_CTA * 68; i += 256) (&sY[0][0])[i] = 0.0f;
    __syncthreads();

    const int cr  = tid >> 4;          // 0..15 (row for copy ops)
    const int cd4 = (tid & 15) * 4;    // 0..60 step 4

    // fixed per-thread tile coords for the exact-256-tile phases
    const int p2_r0 = (tid / 32) * 2;  // P2 / P7: 2r x 2c
    const int p2_n0 = (tid % 32) * 2;
    const int p4_r0 = (tid / 32) * 2;  // P4: 2r x 4c over 128 logical cols
    const int p4_ct = tid % 32;

    for (int step = 0; step < NSTEPS; ++step) {
        const float dt = (step == 0) ? (sts[1] - sts[0]) : (sts[step - 1] - sts[step]);

        // load x(t=step+1) into sC[:,64:128)
        {
            const float4 v = *reinterpret_cast<const float4*>(
                data + (((size_t)(rowbase + cr)) * TT + (step + 1)) * DD + cd4);
            *reinterpret_cast<float4*>(&sC[cr][64 + cd4]) = v;
        }

        // ---- P1: sH[:,0:100) = tanh(bf1 + Y @ Wf1); K=64, 2r x 4c, 200 tiles ----
        for (int t = tid; t < 200; t += 256) {
            const int r0 = (t / 25) * 2, n0 = (t % 25) * 4;
            u64 acc[4] = {0ull, 0ull, 0ull, 0ull};
            tile2x4<64, 100>(Wf1 + n0, &sY[r0][0], &sY[r0 + 1][0], acc);
#pragma unroll
            for (int rr = 0; rr < 2; ++rr) {
                const float2 p0 = unpack2(acc[rr * 2]);
                const float2 p1 = unpack2(acc[rr * 2 + 1]);
                sH[r0 + rr][n0    ] = tanhf(p0.x + sbf1[n0    ]);
                sH[r0 + rr][n0 + 1] = tanhf(p0.y + sbf1[n0 + 1]);
                sH[r0 + rr][n0 + 2] = tanhf(p1.x + sbf1[n0 + 2]);
                sH[r0 + rr][n0 + 3] = tanhf(p1.y + sbf1[n0 + 3]);
            }
        }
        __syncthreads();

        // ---- P2: y_ode = Y + dt*(bf2 + H @ Wf2); K=100, N=64, 2r x 2c, 256 tiles ----
        {
            const int r0 = p2_r0, n0 = p2_n0;
            u64 acc[2] = {0ull, 0ull};
            tile2x2<100, 64>(Wf2 + n0, &sH[r0][0], &sH[r0 + 1][0], acc);
#pragma unroll
            for (int rr = 0; rr < 2; ++rr) {
                const float2 p = unpack2(acc[rr]);
                float v;
                v = sY[r0 + rr][n0    ] + dt * (p.x + sbf2[n0    ]);
                sYO[r0 + rr][n0    ] = v; sC[r0 + rr][n0    ] = v;
                v = sY[r0 + rr][n0 + 1] + dt * (p.y + sbf2[n0 + 1]);
                sYO[r0 + rr][n0 + 1] = v; sC[r0 + rr][n0 + 1] = v;
            }
        }
        __syncthreads();

        // ---- P3: z/r hidden: sH[:,n] = tanh(b + C @ W1); K=128, 4r x 4c, 200 tiles ----
        // logical cols 0..99 -> Wz1, 100..199 -> Wr1
        for (int t = tid; t < 200; t += 256) {
            const int r0 = (t / 50) * 4, n0 = (t % 50) * 4;
            const bool isz = (n0 < 100);
            const int m0 = isz ? n0 : n0 - 100;
            const float* w  = isz ? (Wz1 + m0) : (Wr1 + m0);
            const float* bb = isz ? sbz1 : sbr1;
            u64 acc[8] = {0ull, 0ull, 0ull, 0ull, 0ull, 0ull, 0ull, 0ull};
            tile4x4<128, 100>(w, &sC[r0][0], &sC[r0 + 1][0], &sC[r0 + 2][0], &sC[r0 + 3][0], acc);
#pragma unroll
            for (int rr = 0; rr < 4; ++rr) {
                const float2 p0 = unpack2(acc[rr * 2]);
                const float2 p1 = unpack2(acc[rr * 2 + 1]);
                sH[r0 + rr][n0    ] = tanhf(p0.x + bb[m0    ]);
                sH[r0 + rr][n0 + 1] = tanhf(p0.y + bb[m0 + 1]);
                sH[r0 + rr][n0 + 2] = tanhf(p1.x + bb[m0 + 2]);
                sH[r0 + rr][n0 + 3] = tanhf(p1.y + bb[m0 + 3]);
            }
        }
        __syncthreads();

        // ---- P4: z = sigmoid(bz2 + Hz @ Wz2) -> sZ;
        //          r = sigmoid(br2 + Hr @ Wr2), sC[:,0:64) = y_ode * r  (P5 folded)
        //          K=100, 2r x 4c over 128 logical cols, 256 tiles ----
        {
            const int r0 = p4_r0;
            const int n0 = p4_ct * 4;
            const bool isr = (n0 >= 64);
            const int m0 = isr ? n0 - 64 : n0;
            const float* w  = isr ? (Wr2 + m0) : (Wz2 + m0);
            const float* s0 = &sH[r0][isr ? 100 : 0];
            const float* s1 = &sH[r0 + 1][isr ? 100 : 0];
            u64 acc[4] = {0ull, 0ull, 0ull, 0ull};
            tile2x4<100, 64>(w, s0, s1, acc);
            if (!isr) {
#pragma unroll
                for (int rr = 0; rr < 2; ++rr) {
                    const float2 p0 = unpack2(acc[rr * 2]);
                    const float2 p1 = unpack2(acc[rr * 2 + 1]);
                    sZ[r0 + rr][m0    ] = sigmoidf_fast(p0.x + sbz2[m0    ]);
                    sZ[r0 + rr][m0 + 1] = sigmoidf_fast(p0.y + sbz2[m0 + 1]);
                    sZ[r0 + rr][m0 + 2] = sigmoidf_fast(p1.x + sbz2[m0 + 2]);
                    sZ[r0 + rr][m0 + 3] = sigmoidf_fast(p1.y + sbz2[m0 + 3]);
                }
            } else {
#pragma unroll
                for (int rr = 0; rr < 2; ++rr) {
                    const float2 p0 = unpack2(acc[rr * 2]);
                    const float2 p1 = unpack2(acc[rr * 2 + 1]);
                    sC[r0 + rr][m0    ] = sYO[r0 + rr][m0    ] * sigmoidf_fast(p0.x + sbr2[m0    ]);
                    sC[r0 + rr][m0 + 1] = sYO[r0 + rr][m0 + 1] * sigmoidf_fast(p0.y + sbr2[m0 + 1]);
                    sC[r0 + rr][m0 + 2] = sYO[r0 + rr][m0 + 2] * sigmoidf_fast(p1.x + sbr2[m0 + 2]);
                    sC[r0 + rr][m0 + 3] = sYO[r0 + rr][m0 + 3] * sigmoidf_fast(p1.y + sbr2[m0 + 3]);
                }
            }
        }
        __syncthreads();

        // ---- P6: sH[:,0:100) = tanh(bh1 + CH @ Wh1); K=128, 2r x 4c, 200 tiles ----
        for (int t = tid; t < 200; t += 256) {
            const int r0 = (t / 25) * 2, n0 = (t % 25) * 4;
            u64 acc[4] = {0ull, 0ull, 0ull, 0ull};
            tile2x4<128, 100>(Wh1 + n0, &sC[r0][0], &sC[r0 + 1][0], acc);
#pragma unroll
            for (int rr = 0; rr < 2; ++rr) {
                const float2 p0 = unpack2(acc[rr * 2]);
                const float2 p1 = unpack2(acc[rr * 2 + 1]);
                sH[r0 + rr][n0    ] = tanhf(p0.x + sbh1[n0    ]);
                sH[r0 + rr][n0 + 1] = tanhf(p0.y + sbh1[n0 + 1]);
                sH[r0 + rr][n0 + 2] = tanhf(p1.x + sbh1[n0 + 2]);
                sH[r0 + rr][n0 + 3] = tanhf(p1.y + sbh1[n0 + 3]);
            }
        }
        __syncthreads();

        // ---- P7: h = tanh(bh2 + H @ Wh2); y = (1-z)*h + z*y_ode; K=100, 2r x 2c ----
        {
            const int r0 = p2_r0, n0 = p2_n0;
            u64 acc[2] = {0ull, 0ull};
            tile2x2<100, 64>(Wh2 + n0, &sH[r0][0], &sH[r0 + 1][0], acc);
#pragma unroll
            for (int rr = 0; rr < 2; ++rr) {
                const float2 p = unpack2(acc[rr]);
#pragma unroll
                for (int q = 0; q < 2; ++q) {
                    const int nn = n0 + q;
                    const float h = tanhf(((q == 0) ? p.x : p.y) + sbh2[nn]);
                    const float z = sZ[r0 + rr][nn];
                    const float yo = sYO[r0 + rr][nn];
                    sY[r0 + rr][nn] = (1.0f - z) * h + z * yo;
                }
            }
        }
        __syncthreads();

        // ---- write latent_ys[b][step][:] (read-only on sY; no sync needed after) ----
        if (lat_out) {
            const float4 v = *reinterpret_cast<const float4*>(&sY[cr][cd4]);
            *reinterpret_cast<float4*>(
                lat_out + (((size_t)(rowbase + cr)) * NSTEPS + step) * DD + cd4) = v;
        }
    }

    if (yi_out) {
        const float4 v = *reinterpret_cast<const float4*>(&sY[cr][cd4]);
        *reinterpret_cast<float4*>(yi_out + ((size_t)(rowbase + cr)) * DD + cd4) = v;
    }
}

extern "C" void kernel_launch(void* const* d_in, const int* in_sizes, int n_in,
                              void* d_out, int out_size)
{
    const float* data = (const float*)d_in[0];
    const float* ts   = (const float*)d_in[1];
    const float* Wf1  = (const float*)d_in[2];
    const float* bf1  = (const float*)d_in[3];
    const float* Wf2  = (const float*)d_in[4];
    const float* bf2  = (const float*)d_in[5];
    const float* Wz1  = (const float*)d_in[6];
    const float* bz1  = (const float*)d_in[7];
    const float* Wz2  = (const float*)d_in[8];
    const float* bz2  = (const float*)d_in[9];
    const float* Wr1  = (const float*)d_in[10];
    const float* br1  = (const float*)d_in[11];
    const float* Wr2  = (const float*)d_in[12];
    const float* br2  = (const float*)d_in[13];
    const float* Wh1  = (const float*)d_in[14];
    const float* bh1  = (const float*)d_in[15];
    const float* Wh2  = (const float*)d_in[16];
    const float* bh2  = (const float*)d_in[17];

    const long long latN = 2048LL * 199 * 64;
    const long long yiN  = 2048LL * 64;
    float* out = (float*)d_out;
    float* yi_out = nullptr;
    float* lat_out = nullptr;
    if ((long long)out_size == latN + yiN) { yi_out = out; lat_out = out + yiN; }
    else if ((long long)out_size == latN)  { lat_out = out; }
    else if ((long long)out_size == yiN)   { yi_out = out; }
    else if ((long long)out_size > latN)   { yi_out = out; lat_out = out + yiN; }
    else                                   { lat_out = out; }

    ode_rnn_kernel<<<128, 256>>>(
        data, ts, Wf1, bf1, Wf2, bf2, Wz1, bz1, Wz2, bz2,
        Wr1, br1, Wr2, br2, Wh1, bh1, Wh2, bh2, yi_out, lat_out);
}